// round 1
// baseline (speedup 1.0000x reference)
#include <cuda_runtime.h>
#include <cuda_bf16.h>

// ---------------- problem constants ----------------
#define B_   8
#define Q_   512
#define C_   2048
#define H_   768
#define OUT_ 300
#define K4_  3072   // 4*H

// ---------------- GEMM tiling ----------------
#define BM 128
#define BN 128
#define BK 16
#define TS 132      // padded shared stride (128+4), keeps 16B alignment, breaks conflicts

// ---------------- scratch (static device memory; no runtime allocation) ----------------
static __device__ float g_s[(size_t)B_ * C_ * Q_];     // s, then a in-place (33.5 MB)
static __device__ float g_c2q[(size_t)B_ * C_ * H_];   // c2q (50.3 MB)
static __device__ float g_sc[B_ * C_];
static __device__ float g_sq[B_ * Q_];
static __device__ float g_rowmax[B_ * C_];
static __device__ float g_batt[B_ * C_];
static __device__ float g_q2c[B_ * H_];

// ---------------- reduce helpers ----------------
__device__ __forceinline__ float warpMax(float v) {
    #pragma unroll
    for (int o = 16; o > 0; o >>= 1) v = fmaxf(v, __shfl_xor_sync(0xffffffffu, v, o));
    return v;
}
__device__ __forceinline__ float warpSum(float v) {
    #pragma unroll
    for (int o = 16; o > 0; o >>= 1) v += __shfl_xor_sync(0xffffffffu, v, o);
    return v;
}

// ---------------- sc / sq : one warp per row, dot(row, w) + bias ----------------
__global__ __launch_bounds__(256) void rowdot_kernel(
    const float* __restrict__ X, const float* __restrict__ w,
    const float* __restrict__ bias, int nrows, int which)
{
    int gw = (blockIdx.x * blockDim.x + threadIdx.x) >> 5;
    int lane = threadIdx.x & 31;
    if (gw >= nrows) return;
    const float* x = X + (size_t)gw * H_;
    float s = 0.f;
    #pragma unroll
    for (int i = 0; i < H_ / 32; i++)
        s = fmaf(x[lane + 32 * i], w[lane + 32 * i], s);
    s = warpSum(s);
    if (lane == 0) {
        float r = s + *bias;
        if (which == 0) g_sc[gw] = r; else g_sq[gw] = r;
    }
}

// ---------------- GEMM1: s[b] = (emb2[b] * w_cq) @ emb1[b]^T  + sc + sq + b_cq ----------------
// A: emb2 (M=C_ x K=H_, row-major), B: emb1 (N=Q_ x K=H_, row-major)  -> NT gemm
__global__ __launch_bounds__(256) void gemm1_kernel(
    const float* __restrict__ emb2, const float* __restrict__ emb1,
    const float* __restrict__ w_cq, const float* __restrict__ b_cq_p)
{
    __shared__ float As[BK][TS];
    __shared__ float Bs[BK][TS];
    const int b  = blockIdx.z;
    const int m0 = blockIdx.x * BM;
    const int n0 = blockIdx.y * BN;
    const float* A  = emb2 + (size_t)b * C_ * H_;
    const float* Bm = emb1 + (size_t)b * Q_ * H_;
    float* S = g_s + (size_t)b * C_ * Q_;

    const int tid = threadIdx.x;
    const int tx = tid & 15, ty = tid >> 4;

    float acc[8][8];
    #pragma unroll
    for (int i = 0; i < 8; i++)
        #pragma unroll
        for (int j = 0; j < 8; j++) acc[i][j] = 0.f;

    for (int k0 = 0; k0 < H_; k0 += BK) {
        #pragma unroll
        for (int r = 0; r < 2; r++) {
            int lin = tid + r * 256;            // 0..511 over 512 float4s
            int row = lin >> 2;                 // 0..127
            int kk4 = (lin & 3) << 2;           // 0,4,8,12
            float4 v = *(const float4*)(A + (size_t)(m0 + row) * H_ + k0 + kk4);
            float4 w = *(const float4*)(w_cq + k0 + kk4);
            As[kk4 + 0][row] = v.x * w.x;
            As[kk4 + 1][row] = v.y * w.y;
            As[kk4 + 2][row] = v.z * w.z;
            As[kk4 + 3][row] = v.w * w.w;
            float4 u = *(const float4*)(Bm + (size_t)(n0 + row) * H_ + k0 + kk4);
            Bs[kk4 + 0][row] = u.x;
            Bs[kk4 + 1][row] = u.y;
            Bs[kk4 + 2][row] = u.z;
            Bs[kk4 + 3][row] = u.w;
        }
        __syncthreads();
        #pragma unroll
        for (int kk = 0; kk < BK; kk++) {
            float4 a0 = *(const float4*)&As[kk][ty * 8];
            float4 a1 = *(const float4*)&As[kk][ty * 8 + 4];
            float4 b0 = *(const float4*)&Bs[kk][tx * 8];
            float4 b1 = *(const float4*)&Bs[kk][tx * 8 + 4];
            float av[8] = {a0.x, a0.y, a0.z, a0.w, a1.x, a1.y, a1.z, a1.w};
            float bv[8] = {b0.x, b0.y, b0.z, b0.w, b1.x, b1.y, b1.z, b1.w};
            #pragma unroll
            for (int i = 0; i < 8; i++)
                #pragma unroll
                for (int j = 0; j < 8; j++)
                    acc[i][j] = fmaf(av[i], bv[j], acc[i][j]);
        }
        __syncthreads();
    }

    const float bcq = *b_cq_p;
    float sqv[8];
    #pragma unroll
    for (int j = 0; j < 8; j++) sqv[j] = g_sq[b * Q_ + n0 + tx * 8 + j];
    #pragma unroll
    for (int i = 0; i < 8; i++) {
        int m = m0 + ty * 8 + i;
        float base = g_sc[b * C_ + m] + bcq;
        float4 o0, o1;
        o0.x = acc[i][0] + base + sqv[0];
        o0.y = acc[i][1] + base + sqv[1];
        o0.z = acc[i][2] + base + sqv[2];
        o0.w = acc[i][3] + base + sqv[3];
        o1.x = acc[i][4] + base + sqv[4];
        o1.y = acc[i][5] + base + sqv[5];
        o1.z = acc[i][6] + base + sqv[6];
        o1.w = acc[i][7] + base + sqv[7];
        *(float4*)(S + (size_t)m * Q_ + n0 + tx * 8)     = o0;
        *(float4*)(S + (size_t)m * Q_ + n0 + tx * 8 + 4) = o1;
    }
}

// ---------------- softmax over Q per (b,c) row; also record row max ----------------
__global__ __launch_bounds__(256) void softmax_kernel()
{
    const int row = blockIdx.x;                 // 0 .. B_*C_-1
    float* s = g_s + (size_t)row * Q_;
    const int tid = threadIdx.x;
    const int lane = tid & 31, w = tid >> 5;

    float v0 = s[tid], v1 = s[tid + 256];
    float m = warpMax(fmaxf(v0, v1));
    __shared__ float smx[8];
    if (lane == 0) smx[w] = m;
    __syncthreads();
    if (w == 0) {
        float t = smx[lane & 7];
        t = warpMax(t);
        if (lane == 0) smx[0] = t;
    }
    __syncthreads();
    m = smx[0];
    if (tid == 0) g_rowmax[row] = m;

    float e0 = __expf(v0 - m), e1 = __expf(v1 - m);
    float ss = warpSum(e0 + e1);
    __shared__ float ssm[8];
    if (lane == 0) ssm[w] = ss;
    __syncthreads();
    if (w == 0) {
        float t = (lane < 8) ? ssm[lane] : 0.f;
        t = warpSum(t);
        if (lane == 0) ssm[0] = t;
    }
    __syncthreads();
    float inv = 1.f / ssm[0];
    s[tid]       = e0 * inv;
    s[tid + 256] = e1 * inv;
}

// ---------------- b_att[b,:] = softmax_C(rowmax[b,:]) ----------------
__global__ __launch_bounds__(1024) void batt_kernel()
{
    const int b = blockIdx.x;
    const float* rm = g_rowmax + b * C_;
    const int tid = threadIdx.x;
    const int lane = tid & 31, w = tid >> 5;

    float v0 = rm[tid], v1 = rm[tid + 1024];
    float m = warpMax(fmaxf(v0, v1));
    __shared__ float smx[32];
    if (lane == 0) smx[w] = m;
    __syncthreads();
    if (w == 0) {
        float t = smx[lane];
        t = warpMax(t);
        if (lane == 0) smx[0] = t;
    }
    __syncthreads();
    m = smx[0];

    float e0 = __expf(v0 - m), e1 = __expf(v1 - m);
    float ss = warpSum(e0 + e1);
    __shared__ float ssm[32];
    if (lane == 0) ssm[w] = ss;
    __syncthreads();
    if (w == 0) {
        float t = ssm[lane];
        t = warpSum(t);
        if (lane == 0) ssm[0] = t;
    }
    __syncthreads();
    float inv = 1.f / ssm[0];
    g_batt[b * C_ + tid]        = e0 * inv;
    g_batt[b * C_ + tid + 1024] = e1 * inv;
}

// ---------------- q2c[b,h] = sum_c b_att[b,c] * emb2[b,c,h] ----------------
__global__ __launch_bounds__(256) void q2c_kernel(const float* __restrict__ emb2)
{
    const int b = blockIdx.y;
    const int h = blockIdx.x * 256 + threadIdx.x;
    __shared__ float batt[C_];
    for (int i = threadIdx.x; i < C_; i += 256) batt[i] = g_batt[b * C_ + i];
    __syncthreads();
    const float* e = emb2 + (size_t)b * C_ * H_ + h;
    float acc = 0.f;
    for (int c = 0; c < C_; c++)
        acc = fmaf(batt[c], e[(size_t)c * H_], acc);
    g_q2c[b * H_ + h] = acc;
}

// ---------------- GEMM2: c2q[b] = a[b] @ emb1[b]  (NN gemm) ----------------
// A: g_s (M=C_ x K=Q_, row-major), B: emb1 (K=Q_ x N=H_, row-major)
__global__ __launch_bounds__(256) void gemm2_kernel(const float* __restrict__ emb1)
{
    __shared__ float As[BK][TS];
    __shared__ float Bs[BK][TS];
    const int b  = blockIdx.z;
    const int m0 = blockIdx.x * BM;
    const int n0 = blockIdx.y * BN;
    const float* A  = g_s  + (size_t)b * C_ * Q_;
    const float* Bm = emb1 + (size_t)b * Q_ * H_;
    float* Cc = g_c2q + (size_t)b * C_ * H_;

    const int tid = threadIdx.x;
    const int tx = tid & 15, ty = tid >> 4;

    float acc[8][8];
    #pragma unroll
    for (int i = 0; i < 8; i++)
        #pragma unroll
        for (int j = 0; j < 8; j++) acc[i][j] = 0.f;

    for (int k0 = 0; k0 < Q_; k0 += BK) {
        #pragma unroll
        for (int r = 0; r < 2; r++) {
            int lin = tid + r * 256;
            // A tile (transposed store)
            int row = lin >> 2;
            int kk4 = (lin & 3) << 2;
            float4 v = *(const float4*)(A + (size_t)(m0 + row) * Q_ + k0 + kk4);
            As[kk4 + 0][row] = v.x;
            As[kk4 + 1][row] = v.y;
            As[kk4 + 2][row] = v.z;
            As[kk4 + 3][row] = v.w;
            // B tile (direct store)
            int krow = lin >> 5;                // 0..15
            int c4   = (lin & 31) << 2;         // 0..124
            float4 u = *(const float4*)(Bm + (size_t)(k0 + krow) * H_ + n0 + c4);
            *(float4*)&Bs[krow][c4] = u;
        }
        __syncthreads();
        #pragma unroll
        for (int kk = 0; kk < BK; kk++) {
            float4 a0 = *(const float4*)&As[kk][ty * 8];
            float4 a1 = *(const float4*)&As[kk][ty * 8 + 4];
            float4 b0 = *(const float4*)&Bs[kk][tx * 8];
            float4 b1 = *(const float4*)&Bs[kk][tx * 8 + 4];
            float av[8] = {a0.x, a0.y, a0.z, a0.w, a1.x, a1.y, a1.z, a1.w};
            float bv[8] = {b0.x, b0.y, b0.z, b0.w, b1.x, b1.y, b1.z, b1.w};
            #pragma unroll
            for (int i = 0; i < 8; i++)
                #pragma unroll
                for (int j = 0; j < 8; j++)
                    acc[i][j] = fmaf(av[i], bv[j], acc[i][j]);
        }
        __syncthreads();
    }

    #pragma unroll
    for (int i = 0; i < 8; i++) {
        int m = m0 + ty * 8 + i;
        float4 o0 = {acc[i][0], acc[i][1], acc[i][2], acc[i][3]};
        float4 o1 = {acc[i][4], acc[i][5], acc[i][6], acc[i][7]};
        *(float4*)(Cc + (size_t)m * H_ + n0 + tx * 8)     = o0;
        *(float4*)(Cc + (size_t)m * H_ + n0 + tx * 8 + 4) = o1;
    }
}

// ---------------- GEMM3: out = [emb2, c2q, emb2*c2q, emb2*q2c] @ w_red^T + b_red ----------------
// A is computed on the fly (M=C_ x K=3072), W: (OUT_ x 3072) row-major -> NT gemm
__global__ __launch_bounds__(256) void gemm3_kernel(
    const float* __restrict__ emb2, const float* __restrict__ w_red,
    const float* __restrict__ b_red, float* __restrict__ out)
{
    __shared__ float As[BK][TS];
    __shared__ float Bs[BK][TS];
    const int b  = blockIdx.z;
    const int m0 = blockIdx.x * BM;
    const int n0 = blockIdx.y * BN;

    const int tid = threadIdx.x;
    const int tx = tid & 15, ty = tid >> 4;

    float acc[8][8];
    #pragma unroll
    for (int i = 0; i < 8; i++)
        #pragma unroll
        for (int j = 0; j < 8; j++) acc[i][j] = 0.f;

    for (int k0 = 0; k0 < K4_; k0 += BK) {
        const int seg  = k0 / H_;          // which of the 4 concatenated blocks
        const int koff = k0 - seg * H_;    // offset within the H-wide block
        #pragma unroll
        for (int r = 0; r < 2; r++) {
            int lin = tid + r * 256;
            int row = lin >> 2;
            int kk4 = (lin & 3) << 2;
            size_t idx = (size_t)(b * C_ + m0 + row) * H_ + koff + kk4;
            float4 av;
            if (seg == 0) {
                av = *(const float4*)(emb2 + idx);
            } else if (seg == 1) {
                av = *(const float4*)(g_c2q + idx);
            } else if (seg == 2) {
                float4 e = *(const float4*)(emb2 + idx);
                float4 c = *(const float4*)(g_c2q + idx);
                av.x = e.x * c.x; av.y = e.y * c.y; av.z = e.z * c.z; av.w = e.w * c.w;
            } else {
                float4 e = *(const float4*)(emb2 + idx);
                float4 q = *(const float4*)(g_q2c + b * H_ + koff + kk4);
                av.x = e.x * q.x; av.y = e.y * q.y; av.z = e.z * q.z; av.w = e.w * q.w;
            }
            As[kk4 + 0][row] = av.x;
            As[kk4 + 1][row] = av.y;
            As[kk4 + 2][row] = av.z;
            As[kk4 + 3][row] = av.w;

            float4 u = make_float4(0.f, 0.f, 0.f, 0.f);
            if (n0 + row < OUT_)
                u = *(const float4*)(w_red + (size_t)(n0 + row) * K4_ + k0 + kk4);
            Bs[kk4 + 0][row] = u.x;
            Bs[kk4 + 1][row] = u.y;
            Bs[kk4 + 2][row] = u.z;
            Bs[kk4 + 3][row] = u.w;
        }
        __syncthreads();
        #pragma unroll
        for (int kk = 0; kk < BK; kk++) {
            float4 a0 = *(const float4*)&As[kk][ty * 8];
            float4 a1 = *(const float4*)&As[kk][ty * 8 + 4];
            float4 b0 = *(const float4*)&Bs[kk][tx * 8];
            float4 b1 = *(const float4*)&Bs[kk][tx * 8 + 4];
            float av[8] = {a0.x, a0.y, a0.z, a0.w, a1.x, a1.y, a1.z, a1.w};
            float bv[8] = {b0.x, b0.y, b0.z, b0.w, b1.x, b1.y, b1.z, b1.w};
            #pragma unroll
            for (int i = 0; i < 8; i++)
                #pragma unroll
                for (int j = 0; j < 8; j++)
                    acc[i][j] = fmaf(av[i], bv[j], acc[i][j]);
        }
        __syncthreads();
    }

    #pragma unroll
    for (int i = 0; i < 8; i++) {
        int m = m0 + ty * 8 + i;
        float* orow = out + (size_t)(b * C_ + m) * OUT_;
        #pragma unroll
        for (int j = 0; j < 8; j++) {
            int n = n0 + tx * 8 + j;
            if (n < OUT_) orow[n] = acc[i][j] + b_red[n];
        }
    }
}

// ---------------- launch ----------------
extern "C" void kernel_launch(void* const* d_in, const int* in_sizes, int n_in,
                              void* d_out, int out_size)
{
    const float* emb1  = (const float*)d_in[0];
    const float* emb2  = (const float*)d_in[1];
    const float* w_c   = (const float*)d_in[2];
    const float* b_c   = (const float*)d_in[3];
    const float* w_q   = (const float*)d_in[4];
    const float* b_q   = (const float*)d_in[5];
    const float* w_cq  = (const float*)d_in[6];
    const float* b_cq  = (const float*)d_in[7];
    const float* w_red = (const float*)d_in[8];
    const float* b_red = (const float*)d_in[9];
    float* out = (float*)d_out;

    // sc / sq (independent, tiny)
    rowdot_kernel<<<(B_ * C_ * 32) / 256, 256>>>(emb2, w_c, b_c, B_ * C_, 0);
    rowdot_kernel<<<(B_ * Q_ * 32) / 256, 256>>>(emb1, w_q, b_q, B_ * Q_, 1);

    // s = (emb2*w_cq) @ emb1^T + sc + sq + b_cq
    dim3 g1(C_ / BM, Q_ / BN, B_);
    gemm1_kernel<<<g1, 256>>>(emb2, emb1, w_cq, b_cq);

    // a = softmax_Q(s) in place; rowmax recorded
    softmax_kernel<<<B_ * C_, 256>>>();

    // b_att = softmax_C(rowmax), then q2c = b_att @ emb2
    batt_kernel<<<B_, 1024>>>();
    q2c_kernel<<<dim3(H_ / 256, B_), 256>>>(emb2);

    // c2q = a @ emb1
    dim3 g2(C_ / BM, H_ / BN, B_);
    gemm2_kernel<<<g2, 256>>>(emb1);

    // out = [emb2, c2q, emb2*c2q, emb2*q2c] @ w_red^T + b_red
    dim3 g3(C_ / BM, (OUT_ + BN - 1) / BN, B_);
    gemm3_kernel<<<g3, 256>>>(emb2, w_red, b_red, out);
}

// round 2
// speedup vs baseline: 1.1568x; 1.1568x over previous
#include <cuda_runtime.h>
#include <cuda_bf16.h>

// ---------------- problem constants ----------------
#define B_   8
#define Q_   512
#define C_   2048
#define H_   768
#define OUT_ 300
#define K4_  3072   // 4*H

// ---------------- GEMM tiling ----------------
#define BM 128
#define BN 128
#define BK 16
#define TS 132      // padded shared stride (128+4)

// ---------------- scratch (static device memory; no runtime allocation) ----------------
static __device__ float g_s[(size_t)B_ * C_ * Q_];     // s, then a in-place
static __device__ float g_c2q[(size_t)B_ * C_ * H_];   // c2q
static __device__ float g_emb1s[(size_t)B_ * Q_ * H_]; // emb1 * w_cq
static __device__ float g_sc[B_ * C_];
static __device__ float g_sq[B_ * Q_];
static __device__ float g_rowmax[B_ * C_];
static __device__ float g_batt[B_ * C_];
static __device__ float g_q2c[B_ * H_];

// ---------------- packed f32x2 helpers ----------------
__device__ __forceinline__ void ffma2(unsigned long long &d, unsigned long long a, unsigned long long b) {
    asm("fma.rn.f32x2 %0, %1, %2, %0;" : "+l"(d) : "l"(a), "l"(b));
}
__device__ __forceinline__ unsigned long long dup2(float x) {
    unsigned long long r;
    asm("mov.b64 %0, {%1, %1};" : "=l"(r) : "f"(x));
    return r;
}

// ---------------- reduce helpers ----------------
__device__ __forceinline__ float warpMax(float v) {
    #pragma unroll
    for (int o = 16; o > 0; o >>= 1) v = fmaxf(v, __shfl_xor_sync(0xffffffffu, v, o));
    return v;
}
__device__ __forceinline__ float warpSum(float v) {
    #pragma unroll
    for (int o = 16; o > 0; o >>= 1) v += __shfl_xor_sync(0xffffffffu, v, o);
    return v;
}

// ---------------- inner product step on one K-tile ----------------
__device__ __forceinline__ void mm_tile(
    const float (*__restrict__ As)[TS], const float (*__restrict__ Bs)[TS],
    int ty, int tx, unsigned long long (&acc)[8][4])
{
    #pragma unroll
    for (int kk = 0; kk < BK; kk++) {
        float4 a0 = *(const float4*)&As[kk][ty * 8];
        float4 a1 = *(const float4*)&As[kk][ty * 8 + 4];
        float4 b0 = *(const float4*)&Bs[kk][tx * 8];
        float4 b1 = *(const float4*)&Bs[kk][tx * 8 + 4];
        ulonglong2 bl0 = *(ulonglong2*)&b0;
        ulonglong2 bl1 = *(ulonglong2*)&b1;
        unsigned long long bv[4] = {bl0.x, bl0.y, bl1.x, bl1.y};
        float av[8] = {a0.x, a0.y, a0.z, a0.w, a1.x, a1.y, a1.z, a1.w};
        #pragma unroll
        for (int i = 0; i < 8; i++) {
            unsigned long long ad = dup2(av[i]);
            #pragma unroll
            for (int j = 0; j < 4; j++) ffma2(acc[i][j], ad, bv[j]);
        }
    }
}

// ---------------- emb1s = emb1 * w_cq ----------------
__global__ __launch_bounds__(256) void scale_emb1_kernel(
    const float* __restrict__ emb1, const float* __restrict__ w_cq)
{
    int p = (blockIdx.x * 256 + threadIdx.x) * 4;   // element index
    int h = p % H_;
    float4 v = *(const float4*)(emb1 + p);
    float4 w = *(const float4*)(w_cq + h);
    v.x *= w.x; v.y *= w.y; v.z *= w.z; v.w *= w.w;
    *(float4*)(g_emb1s + p) = v;
}

// ---------------- sc / sq : one warp per row ----------------
__global__ __launch_bounds__(256) void rowdot_kernel(
    const float* __restrict__ X, const float* __restrict__ w,
    const float* __restrict__ bias, int nrows, int which)
{
    int gw = (blockIdx.x * blockDim.x + threadIdx.x) >> 5;
    int lane = threadIdx.x & 31;
    if (gw >= nrows) return;
    const float* x = X + (size_t)gw * H_;
    float s = 0.f;
    #pragma unroll
    for (int i = 0; i < H_ / 32; i++)
        s = fmaf(x[lane + 32 * i], w[lane + 32 * i], s);
    s = warpSum(s);
    if (lane == 0) {
        float r = s + *bias;
        if (which == 0) g_sc[gw] = r; else g_sq[gw] = r;
    }
}

// ---------------- GEMM1: s[b] = emb2[b] @ emb1s[b]^T + sc + sq + b_cq (NT) ----------------
__global__ __launch_bounds__(256) void gemm1_kernel(
    const float* __restrict__ emb2, const float* __restrict__ b_cq_p)
{
    __shared__ float As[2][BK][TS];
    __shared__ float Bs[2][BK][TS];
    const int b  = blockIdx.z;
    const int m0 = blockIdx.x * BM;
    const int n0 = blockIdx.y * BN;
    const float* A  = emb2    + (size_t)b * C_ * H_;
    const float* Bm = g_emb1s + (size_t)b * Q_ * H_;
    float* S = g_s + (size_t)b * C_ * Q_;

    const int tid = threadIdx.x;
    const int tx = tid & 15, ty = tid >> 4;
    const int lrow0 = tid >> 2,            lrow1 = (tid + 256) >> 2;
    const int lk0   = (tid & 3) << 2,      lk1   = ((tid + 256) & 3) << 2; // same as lk0

    unsigned long long acc[8][4];
    #pragma unroll
    for (int i = 0; i < 8; i++)
        #pragma unroll
        for (int j = 0; j < 4; j++) acc[i][j] = 0ull;

    float4 pa0, pa1, pb0, pb1;
    // preload k0 = 0
    pa0 = *(const float4*)(A  + (size_t)(m0 + lrow0) * H_ + lk0);
    pa1 = *(const float4*)(A  + (size_t)(m0 + lrow1) * H_ + lk1);
    pb0 = *(const float4*)(Bm + (size_t)(n0 + lrow0) * H_ + lk0);
    pb1 = *(const float4*)(Bm + (size_t)(n0 + lrow1) * H_ + lk1);
    {
        As[0][lk0+0][lrow0]=pa0.x; As[0][lk0+1][lrow0]=pa0.y; As[0][lk0+2][lrow0]=pa0.z; As[0][lk0+3][lrow0]=pa0.w;
        As[0][lk1+0][lrow1]=pa1.x; As[0][lk1+1][lrow1]=pa1.y; As[0][lk1+2][lrow1]=pa1.z; As[0][lk1+3][lrow1]=pa1.w;
        Bs[0][lk0+0][lrow0]=pb0.x; Bs[0][lk0+1][lrow0]=pb0.y; Bs[0][lk0+2][lrow0]=pb0.z; Bs[0][lk0+3][lrow0]=pb0.w;
        Bs[0][lk1+0][lrow1]=pb1.x; Bs[0][lk1+1][lrow1]=pb1.y; Bs[0][lk1+2][lrow1]=pb1.z; Bs[0][lk1+3][lrow1]=pb1.w;
    }
    __syncthreads();

    int cur = 0;
    for (int k0 = BK; k0 < H_; k0 += BK) {
        pa0 = *(const float4*)(A  + (size_t)(m0 + lrow0) * H_ + k0 + lk0);
        pa1 = *(const float4*)(A  + (size_t)(m0 + lrow1) * H_ + k0 + lk1);
        pb0 = *(const float4*)(Bm + (size_t)(n0 + lrow0) * H_ + k0 + lk0);
        pb1 = *(const float4*)(Bm + (size_t)(n0 + lrow1) * H_ + k0 + lk1);

        mm_tile(As[cur], Bs[cur], ty, tx, acc);

        int nxt = cur ^ 1;
        As[nxt][lk0+0][lrow0]=pa0.x; As[nxt][lk0+1][lrow0]=pa0.y; As[nxt][lk0+2][lrow0]=pa0.z; As[nxt][lk0+3][lrow0]=pa0.w;
        As[nxt][lk1+0][lrow1]=pa1.x; As[nxt][lk1+1][lrow1]=pa1.y; As[nxt][lk1+2][lrow1]=pa1.z; As[nxt][lk1+3][lrow1]=pa1.w;
        Bs[nxt][lk0+0][lrow0]=pb0.x; Bs[nxt][lk0+1][lrow0]=pb0.y; Bs[nxt][lk0+2][lrow0]=pb0.z; Bs[nxt][lk0+3][lrow0]=pb0.w;
        Bs[nxt][lk1+0][lrow1]=pb1.x; Bs[nxt][lk1+1][lrow1]=pb1.y; Bs[nxt][lk1+2][lrow1]=pb1.z; Bs[nxt][lk1+3][lrow1]=pb1.w;
        __syncthreads();
        cur = nxt;
    }
    mm_tile(As[cur], Bs[cur], ty, tx, acc);

    const float bcq = *b_cq_p;
    float sqv[8];
    #pragma unroll
    for (int j = 0; j < 8; j++) sqv[j] = g_sq[b * Q_ + n0 + tx * 8 + j];
    #pragma unroll
    for (int i = 0; i < 8; i++) {
        int m = m0 + ty * 8 + i;
        float base = g_sc[b * C_ + m] + bcq;
        float av[8];
        #pragma unroll
        for (int j = 0; j < 4; j++) {
            float2 p = *(float2*)&acc[i][j];
            av[2*j] = p.x; av[2*j+1] = p.y;
        }
        float4 o0 = {av[0]+base+sqv[0], av[1]+base+sqv[1], av[2]+base+sqv[2], av[3]+base+sqv[3]};
        float4 o1 = {av[4]+base+sqv[4], av[5]+base+sqv[5], av[6]+base+sqv[6], av[7]+base+sqv[7]};
        *(float4*)(S + (size_t)m * Q_ + n0 + tx * 8)     = o0;
        *(float4*)(S + (size_t)m * Q_ + n0 + tx * 8 + 4) = o1;
    }
}

// ---------------- softmax over Q per (b,c) row; record row max ----------------
__global__ __launch_bounds__(256) void softmax_kernel()
{
    const int row = blockIdx.x;
    float* s = g_s + (size_t)row * Q_;
    const int tid = threadIdx.x;
    const int lane = tid & 31, w = tid >> 5;

    float v0 = s[tid], v1 = s[tid + 256];
    float m = warpMax(fmaxf(v0, v1));
    __shared__ float smx[8];
    if (lane == 0) smx[w] = m;
    __syncthreads();
    if (w == 0) {
        float t = smx[lane & 7];
        t = warpMax(t);
        if (lane == 0) smx[0] = t;
    }
    __syncthreads();
    m = smx[0];
    if (tid == 0) g_rowmax[row] = m;

    float e0 = __expf(v0 - m), e1 = __expf(v1 - m);
    float ss = warpSum(e0 + e1);
    __shared__ float ssm[8];
    if (lane == 0) ssm[w] = ss;
    __syncthreads();
    if (w == 0) {
        float t = (lane < 8) ? ssm[lane] : 0.f;
        t = warpSum(t);
        if (lane == 0) ssm[0] = t;
    }
    __syncthreads();
    float inv = 1.f / ssm[0];
    s[tid]       = e0 * inv;
    s[tid + 256] = e1 * inv;
}

// ---------------- b_att[b,:] = softmax_C(rowmax[b,:]) ----------------
__global__ __launch_bounds__(1024) void batt_kernel()
{
    const int b = blockIdx.x;
    const float* rm = g_rowmax + b * C_;
    const int tid = threadIdx.x;
    const int lane = tid & 31, w = tid >> 5;

    float v0 = rm[tid], v1 = rm[tid + 1024];
    float m = warpMax(fmaxf(v0, v1));
    __shared__ float smx[32];
    if (lane == 0) smx[w] = m;
    __syncthreads();
    if (w == 0) {
        float t = smx[lane];
        t = warpMax(t);
        if (lane == 0) smx[0] = t;
    }
    __syncthreads();
    m = smx[0];

    float e0 = __expf(v0 - m), e1 = __expf(v1 - m);
    float ss = warpSum(e0 + e1);
    __shared__ float ssm[32];
    if (lane == 0) ssm[w] = ss;
    __syncthreads();
    if (w == 0) {
        float t = ssm[lane];
        t = warpSum(t);
        if (lane == 0) ssm[0] = t;
    }
    __syncthreads();
    float inv = 1.f / ssm[0];
    g_batt[b * C_ + tid]        = e0 * inv;
    g_batt[b * C_ + tid + 1024] = e1 * inv;
}

// ---------------- q2c[b,h] = sum_c b_att[b,c] * emb2[b,c,h] ----------------
__global__ __launch_bounds__(256) void q2c_kernel(const float* __restrict__ emb2)
{
    const int b = blockIdx.y;
    const int h = blockIdx.x * 256 + threadIdx.x;
    __shared__ float batt[C_];
    for (int i = threadIdx.x; i < C_; i += 256) batt[i] = g_batt[b * C_ + i];
    __syncthreads();
    const float* e = emb2 + (size_t)b * C_ * H_ + h;
    float acc = 0.f;
    for (int c = 0; c < C_; c++)
        acc = fmaf(batt[c], e[(size_t)c * H_], acc);
    g_q2c[b * H_ + h] = acc;
}

// ---------------- GEMM2: c2q[b] = a[b] @ emb1[b]  (NN) ----------------
__global__ __launch_bounds__(256) void gemm2_kernel(const float* __restrict__ emb1)
{
    __shared__ float As[2][BK][TS];
    __shared__ float Bs[2][BK][TS];
    const int b  = blockIdx.z;
    const int m0 = blockIdx.x * BM;
    const int n0 = blockIdx.y * BN;
    const float* A  = g_s  + (size_t)b * C_ * Q_;
    const float* Bm = emb1 + (size_t)b * Q_ * H_;
    float* Cc = g_c2q + (size_t)b * C_ * H_;

    const int tid = threadIdx.x;
    const int tx = tid & 15, ty = tid >> 4;
    const int lrow0 = tid >> 2,       lrow1 = (tid + 256) >> 2;
    const int lk0   = (tid & 3) << 2;
    const int krow0 = tid >> 5,       krow1 = (tid + 256) >> 5;
    const int c40   = (tid & 31) << 2;

    unsigned long long acc[8][4];
    #pragma unroll
    for (int i = 0; i < 8; i++)
        #pragma unroll
        for (int j = 0; j < 4; j++) acc[i][j] = 0ull;

    float4 pa0, pa1, pb0, pb1;
    pa0 = *(const float4*)(A  + (size_t)(m0 + lrow0) * Q_ + lk0);
    pa1 = *(const float4*)(A  + (size_t)(m0 + lrow1) * Q_ + lk0);
    pb0 = *(const float4*)(Bm + (size_t)(krow0) * H_ + n0 + c40);
    pb1 = *(const float4*)(Bm + (size_t)(krow1) * H_ + n0 + c40);
    {
        As[0][lk0+0][lrow0]=pa0.x; As[0][lk0+1][lrow0]=pa0.y; As[0][lk0+2][lrow0]=pa0.z; As[0][lk0+3][lrow0]=pa0.w;
        As[0][lk0+0][lrow1]=pa1.x; As[0][lk0+1][lrow1]=pa1.y; As[0][lk0+2][lrow1]=pa1.z; As[0][lk0+3][lrow1]=pa1.w;
        *(float4*)&Bs[0][krow0][c40] = pb0;
        *(float4*)&Bs[0][krow1][c40] = pb1;
    }
    __syncthreads();

    int cur = 0;
    for (int k0 = BK; k0 < Q_; k0 += BK) {
        pa0 = *(const float4*)(A  + (size_t)(m0 + lrow0) * Q_ + k0 + lk0);
        pa1 = *(const float4*)(A  + (size_t)(m0 + lrow1) * Q_ + k0 + lk0);
        pb0 = *(const float4*)(Bm + (size_t)(k0 + krow0) * H_ + n0 + c40);
        pb1 = *(const float4*)(Bm + (size_t)(k0 + krow1) * H_ + n0 + c40);

        mm_tile(As[cur], Bs[cur], ty, tx, acc);

        int nxt = cur ^ 1;
        As[nxt][lk0+0][lrow0]=pa0.x; As[nxt][lk0+1][lrow0]=pa0.y; As[nxt][lk0+2][lrow0]=pa0.z; As[nxt][lk0+3][lrow0]=pa0.w;
        As[nxt][lk0+0][lrow1]=pa1.x; As[nxt][lk0+1][lrow1]=pa1.y; As[nxt][lk0+2][lrow1]=pa1.z; As[nxt][lk0+3][lrow1]=pa1.w;
        *(float4*)&Bs[nxt][krow0][c40] = pb0;
        *(float4*)&Bs[nxt][krow1][c40] = pb1;
        __syncthreads();
        cur = nxt;
    }
    mm_tile(As[cur], Bs[cur], ty, tx, acc);

    #pragma unroll
    for (int i = 0; i < 8; i++) {
        int m = m0 + ty * 8 + i;
        float av[8];
        #pragma unroll
        for (int j = 0; j < 4; j++) {
            float2 p = *(float2*)&acc[i][j];
            av[2*j] = p.x; av[2*j+1] = p.y;
        }
        float4 o0 = {av[0], av[1], av[2], av[3]};
        float4 o1 = {av[4], av[5], av[6], av[7]};
        *(float4*)(Cc + (size_t)m * H_ + n0 + tx * 8)     = o0;
        *(float4*)(Cc + (size_t)m * H_ + n0 + tx * 8 + 4) = o1;
    }
}

// ---------------- GEMM3: out = [emb2, c2q, emb2*c2q, emb2*q2c] @ w_red^T + b_red (NT) ----------------
__device__ __forceinline__ float4 gemm3_loadA(
    const float* __restrict__ emb2, int b, int row_g, int seg, int koff)
{
    size_t idx = (size_t)row_g * H_ + koff;
    if (seg == 0) {
        return *(const float4*)(emb2 + idx);
    } else if (seg == 1) {
        return *(const float4*)(g_c2q + idx);
    } else if (seg == 2) {
        float4 e = *(const float4*)(emb2 + idx);
        float4 c = *(const float4*)(g_c2q + idx);
        return make_float4(e.x*c.x, e.y*c.y, e.z*c.z, e.w*c.w);
    } else {
        float4 e = *(const float4*)(emb2 + idx);
        float4 q = *(const float4*)(g_q2c + b * H_ + koff);
        return make_float4(e.x*q.x, e.y*q.y, e.z*q.z, e.w*q.w);
    }
}

__global__ __launch_bounds__(256) void gemm3_kernel(
    const float* __restrict__ emb2, const float* __restrict__ w_red,
    const float* __restrict__ b_red, float* __restrict__ out)
{
    __shared__ float As[2][BK][TS];
    __shared__ float Bs[2][BK][TS];
    const int b  = blockIdx.z;
    const int m0 = blockIdx.x * BM;
    const int n0 = blockIdx.y * BN;

    const int tid = threadIdx.x;
    const int tx = tid & 15, ty = tid >> 4;
    const int lrow0 = tid >> 2, lrow1 = (tid + 256) >> 2;
    const int lk0   = (tid & 3) << 2;

    unsigned long long acc[8][4];
    #pragma unroll
    for (int i = 0; i < 8; i++)
        #pragma unroll
        for (int j = 0; j < 4; j++) acc[i][j] = 0ull;

    const int rg0 = b * C_ + m0 + lrow0;
    const int rg1 = b * C_ + m0 + lrow1;
    const bool wok0 = (n0 + lrow0) < OUT_;
    const bool wok1 = (n0 + lrow1) < OUT_;
    const float* wr0 = w_red + (size_t)(n0 + lrow0) * K4_;
    const float* wr1 = w_red + (size_t)(n0 + lrow1) * K4_;

    float4 pa0, pa1, pb0, pb1;
    pa0 = gemm3_loadA(emb2, b, rg0, 0, lk0);
    pa1 = gemm3_loadA(emb2, b, rg1, 0, lk0);
    pb0 = wok0 ? *(const float4*)(wr0 + lk0) : make_float4(0,0,0,0);
    pb1 = wok1 ? *(const float4*)(wr1 + lk0) : make_float4(0,0,0,0);
    {
        As[0][lk0+0][lrow0]=pa0.x; As[0][lk0+1][lrow0]=pa0.y; As[0][lk0+2][lrow0]=pa0.z; As[0][lk0+3][lrow0]=pa0.w;
        As[0][lk0+0][lrow1]=pa1.x; As[0][lk0+1][lrow1]=pa1.y; As[0][lk0+2][lrow1]=pa1.z; As[0][lk0+3][lrow1]=pa1.w;
        Bs[0][lk0+0][lrow0]=pb0.x; Bs[0][lk0+1][lrow0]=pb0.y; Bs[0][lk0+2][lrow0]=pb0.z; Bs[0][lk0+3][lrow0]=pb0.w;
        Bs[0][lk0+0][lrow1]=pb1.x; Bs[0][lk0+1][lrow1]=pb1.y; Bs[0][lk0+2][lrow1]=pb1.z; Bs[0][lk0+3][lrow1]=pb1.w;
    }
    __syncthreads();

    int cur = 0;
    for (int k0 = BK; k0 < K4_; k0 += BK) {
        const int seg  = k0 / H_;
        const int koff = k0 - seg * H_;
        pa0 = gemm3_loadA(emb2, b, rg0, seg, koff + lk0);
        pa1 = gemm3_loadA(emb2, b, rg1, seg, koff + lk0);
        pb0 = wok0 ? *(const float4*)(wr0 + k0 + lk0) : make_float4(0,0,0,0);
        pb1 = wok1 ? *(const float4*)(wr1 + k0 + lk0) : make_float4(0,0,0,0);

        mm_tile(As[cur], Bs[cur], ty, tx, acc);

        int nxt = cur ^ 1;
        As[nxt][lk0+0][lrow0]=pa0.x; As[nxt][lk0+1][lrow0]=pa0.y; As[nxt][lk0+2][lrow0]=pa0.z; As[nxt][lk0+3][lrow0]=pa0.w;
        As[nxt][lk0+0][lrow1]=pa1.x; As[nxt][lk0+1][lrow1]=pa1.y; As[nxt][lk0+2][lrow1]=pa1.z; As[nxt][lk0+3][lrow1]=pa1.w;
        Bs[nxt][lk0+0][lrow0]=pb0.x; Bs[nxt][lk0+1][lrow0]=pb0.y; Bs[nxt][lk0+2][lrow0]=pb0.z; Bs[nxt][lk0+3][lrow0]=pb0.w;
        Bs[nxt][lk0+0][lrow1]=pb1.x; Bs[nxt][lk0+1][lrow1]=pb1.y; Bs[nxt][lk0+2][lrow1]=pb1.z; Bs[nxt][lk0+3][lrow1]=pb1.w;
        __syncthreads();
        cur = nxt;
    }
    mm_tile(As[cur], Bs[cur], ty, tx, acc);

    #pragma unroll
    for (int i = 0; i < 8; i++) {
        int m = m0 + ty * 8 + i;
        float* orow = out + (size_t)(b * C_ + m) * OUT_;
        #pragma unroll
        for (int j = 0; j < 4; j++) {
            float2 p = *(float2*)&acc[i][j];
            int n = n0 + tx * 8 + 2 * j;
            if (n     < OUT_) orow[n]     = p.x + b_red[n];
            if (n + 1 < OUT_) orow[n + 1] = p.y + b_red[n + 1];
        }
    }
}

// ---------------- launch ----------------
extern "C" void kernel_launch(void* const* d_in, const int* in_sizes, int n_in,
                              void* d_out, int out_size)
{
    const float* emb1  = (const float*)d_in[0];
    const float* emb2  = (const float*)d_in[1];
    const float* w_c   = (const float*)d_in[2];
    const float* b_c   = (const float*)d_in[3];
    const float* w_q   = (const float*)d_in[4];
    const float* b_q   = (const float*)d_in[5];
    const float* w_cq  = (const float*)d_in[6];
    const float* b_cq  = (const float*)d_in[7];
    const float* w_red = (const float*)d_in[8];
    const float* b_red = (const float*)d_in[9];
    float* out = (float*)d_out;

    // prescale emb1 by w_cq; sc / sq (independent, tiny)
    scale_emb1_kernel<<<(B_ * Q_ * H_ / 4) / 256, 256>>>(emb1, w_cq);
    rowdot_kernel<<<(B_ * C_ * 32) / 256, 256>>>(emb2, w_c, b_c, B_ * C_, 0);
    rowdot_kernel<<<(B_ * Q_ * 32) / 256, 256>>>(emb1, w_q, b_q, B_ * Q_, 1);

    // s = emb2 @ emb1s^T + sc + sq + b_cq
    dim3 g1(C_ / BM, Q_ / BN, B_);
    gemm1_kernel<<<g1, 256>>>(emb2, b_cq);

    // a = softmax_Q(s) in place; rowmax recorded
    softmax_kernel<<<B_ * C_, 256>>>();

    // b_att = softmax_C(rowmax), then q2c = b_att @ emb2
    batt_kernel<<<B_, 1024>>>();
    q2c_kernel<<<dim3(H_ / 256, B_), 256>>>(emb2);

    // c2q = a @ emb1
    dim3 g2(C_ / BM, H_ / BN, B_);
    gemm2_kernel<<<g2, 256>>>(emb1);

    // out = [emb2, c2q, emb2*c2q, emb2*q2c] @ w_red^T + b_red
    dim3 g3(C_ / BM, (OUT_ + BN - 1) / BN, B_);
    gemm3_kernel<<<g3, 256>>>(emb2, w_red, b_red, out);
}

// round 4
// speedup vs baseline: 2.7481x; 2.3756x over previous
#include <cuda_runtime.h>
#include <cuda_bf16.h>
#include <cstdint>

// ---------------- problem constants ----------------
#define B_   8
#define Q_   512
#define C_   2048
#define H_   768
#define OUT_ 300
#define K4_  3072   // 4*H

// ---------------- GEMM tiling ----------------
#define BM 128
#define BN 64
#define BK 64                  // bf16 k per chunk (128B rows)
#define AT_BYTES 16384         // 128 x 128B
#define BT_BYTES 8192          // 64 x 128B
#define OFF_AL 16384
#define OFF_BH 32768
#define OFF_BL 40960
#define STAGE_BYTES 49152
#define SMEM_TOTAL (2 * STAGE_BYTES)   // 96 KB

#define SWZ(x) ((x) ^ (((x) >> 3) & 0x70))

// ---------------- f32 scratch ----------------
static __device__ __align__(16) float g_s[(size_t)B_ * C_ * Q_];
static __device__ __align__(16) float g_c2q[(size_t)B_ * C_ * H_];
static __device__ float g_sc[B_ * C_];
static __device__ float g_sq[B_ * Q_];
static __device__ float g_rowmax[B_ * C_];
static __device__ float g_batt[B_ * C_];
static __device__ float g_q2c[B_ * H_];

// ---------------- bf16 hi/lo planes ----------------
static __device__ __align__(16) __nv_bfloat16 p_e2h[(size_t)B_ * C_ * H_];
static __device__ __align__(16) __nv_bfloat16 p_e2l[(size_t)B_ * C_ * H_];
static __device__ __align__(16) __nv_bfloat16 p_b1h[(size_t)B_ * Q_ * H_];   // emb1*w_cq
static __device__ __align__(16) __nv_bfloat16 p_b1l[(size_t)B_ * Q_ * H_];
static __device__ __align__(16) __nv_bfloat16 p_e1th[(size_t)B_ * H_ * Q_];  // emb1^T
static __device__ __align__(16) __nv_bfloat16 p_e1tl[(size_t)B_ * H_ * Q_];
static __device__ __align__(16) __nv_bfloat16 p_ah[(size_t)B_ * C_ * Q_];    // softmax probs
static __device__ __align__(16) __nv_bfloat16 p_al[(size_t)B_ * C_ * Q_];
static __device__ __align__(16) __nv_bfloat16 p_cqh[(size_t)B_ * C_ * H_];   // c2q
static __device__ __align__(16) __nv_bfloat16 p_cql[(size_t)B_ * C_ * H_];
static __device__ __align__(16) __nv_bfloat16 p_ech[(size_t)B_ * C_ * H_];   // emb2*c2q
static __device__ __align__(16) __nv_bfloat16 p_ecl[(size_t)B_ * C_ * H_];
static __device__ __align__(16) __nv_bfloat16 p_eqh[(size_t)B_ * C_ * H_];   // emb2*q2c
static __device__ __align__(16) __nv_bfloat16 p_eql[(size_t)B_ * C_ * H_];
static __device__ __align__(16) __nv_bfloat16 p_wh[(size_t)OUT_ * K4_];      // w_red
static __device__ __align__(16) __nv_bfloat16 p_wl[(size_t)OUT_ * K4_];

// ---------------- asm helpers ----------------
__device__ __forceinline__ uint32_t smem_u32(const void* p) {
    uint32_t a;
    asm("{ .reg .u64 t; cvta.to.shared.u64 t, %1; cvt.u32.u64 %0, t; }" : "=r"(a) : "l"(p));
    return a;
}
__device__ __forceinline__ void cpa16(uint32_t dst, const void* src) {
    asm volatile("cp.async.cg.shared.global [%0], [%1], 16;" :: "r"(dst), "l"(src) : "memory");
}
__device__ __forceinline__ void cpa16z(uint32_t dst, const void* src, int szbytes) {
    asm volatile("cp.async.cg.shared.global [%0], [%1], 16, %2;" :: "r"(dst), "l"(src), "r"(szbytes) : "memory");
}
__device__ __forceinline__ void cpa_commit() {
    asm volatile("cp.async.commit_group;" ::: "memory");
}
template<int N>
__device__ __forceinline__ void cpa_wait() {
    asm volatile("cp.async.wait_group %0;" :: "n"(N) : "memory");
}
__device__ __forceinline__ void ldsm4(uint32_t (&r)[4], uint32_t addr) {
    asm volatile("ldmatrix.sync.aligned.m8n8.x4.shared.b16 {%0,%1,%2,%3}, [%4];"
        : "=r"(r[0]), "=r"(r[1]), "=r"(r[2]), "=r"(r[3]) : "r"(addr));
}
__device__ __forceinline__ void mma_bf16(float (&d)[4], const uint32_t (&a)[4], uint32_t b0, uint32_t b1) {
    asm volatile("mma.sync.aligned.m16n8k16.row.col.f32.bf16.bf16.f32 "
        "{%0,%1,%2,%3}, {%4,%5,%6,%7}, {%8,%9}, {%0,%1,%2,%3};"
        : "+f"(d[0]), "+f"(d[1]), "+f"(d[2]), "+f"(d[3])
        : "r"(a[0]), "r"(a[1]), "r"(a[2]), "r"(a[3]), "r"(b0), "r"(b1));
}

// ---------------- split helpers ----------------
__device__ __forceinline__ void split4(float4 v, uint2& hi, uint2& lo) {
    __nv_bfloat162 h01 = __floats2bfloat162_rn(v.x, v.y);
    __nv_bfloat162 h23 = __floats2bfloat162_rn(v.z, v.w);
    float lx = v.x - __bfloat162float(h01.x);
    float ly = v.y - __bfloat162float(h01.y);
    float lz = v.z - __bfloat162float(h23.x);
    float lw = v.w - __bfloat162float(h23.y);
    __nv_bfloat162 l01 = __floats2bfloat162_rn(lx, ly);
    __nv_bfloat162 l23 = __floats2bfloat162_rn(lz, lw);
    hi.x = *(uint32_t*)&h01; hi.y = *(uint32_t*)&h23;
    lo.x = *(uint32_t*)&l01; lo.y = *(uint32_t*)&l23;
}

// ---------------- prep kernels ----------------
__global__ __launch_bounds__(256) void prep_emb2_kernel(const float* __restrict__ emb2) {
    size_t p = ((size_t)blockIdx.x * 256 + threadIdx.x) * 4;
    float4 v = *(const float4*)(emb2 + p);
    uint2 h, l; split4(v, h, l);
    *(uint2*)(p_e2h + p) = h;
    *(uint2*)(p_e2l + p) = l;
}

__global__ __launch_bounds__(256) void prep_b1_kernel(const float* __restrict__ emb1,
                                                      const float* __restrict__ w_cq) {
    size_t p = ((size_t)blockIdx.x * 256 + threadIdx.x) * 4;
    int hcol = (int)(p % H_);
    float4 v = *(const float4*)(emb1 + p);
    float4 w = *(const float4*)(w_cq + hcol);
    v.x *= w.x; v.y *= w.y; v.z *= w.z; v.w *= w.w;
    uint2 h, l; split4(v, h, l);
    *(uint2*)(p_b1h + p) = h;
    *(uint2*)(p_b1l + p) = l;
}

// emb1^T split: e1t[b,h,q] = emb1[b,q,h]
__global__ __launch_bounds__(256) void prep_e1t_kernel(const float* __restrict__ emb1) {
    __shared__ float sm[32][33];
    const int b = blockIdx.z, h0 = blockIdx.y * 32, q0 = blockIdx.x * 32;
    const int tx = threadIdx.x & 31, ty = threadIdx.x >> 5;
    #pragma unroll
    for (int i = 0; i < 4; i++)
        sm[ty + 8 * i][tx] = emb1[(size_t)(b * Q_ + q0 + ty + 8 * i) * H_ + h0 + tx];
    __syncthreads();
    #pragma unroll
    for (int i = 0; i < 4; i++) {
        float v = sm[tx][ty + 8 * i];
        __nv_bfloat16 h = __float2bfloat16(v);
        __nv_bfloat16 l = __float2bfloat16(v - __bfloat162float(h));
        size_t o = (size_t)(b * H_ + h0 + ty + 8 * i) * Q_ + q0 + tx;
        p_e1th[o] = h;
        p_e1tl[o] = l;
    }
}

__global__ __launch_bounds__(256) void prep_wred_kernel(const float* __restrict__ w_red) {
    size_t p = ((size_t)blockIdx.x * 256 + threadIdx.x) * 4;
    float4 v = *(const float4*)(w_red + p);
    uint2 h, l; split4(v, h, l);
    *(uint2*)(p_wh + p) = h;
    *(uint2*)(p_wl + p) = l;
}

__global__ __launch_bounds__(256) void prep_g3_kernel(const float* __restrict__ emb2) {
    size_t p = ((size_t)blockIdx.x * 256 + threadIdx.x) * 4;
    int hcol = (int)(p % H_);
    int b = (int)(p / ((size_t)C_ * H_));
    float4 e = *(const float4*)(emb2 + p);
    float4 cq = *(const float4*)(g_c2q + p);
    float4 qv = *(const float4*)(g_q2c + b * H_ + hcol);
    uint2 h, l;
    split4(cq, h, l);
    *(uint2*)(p_cqh + p) = h; *(uint2*)(p_cql + p) = l;
    float4 ec = make_float4(e.x * cq.x, e.y * cq.y, e.z * cq.z, e.w * cq.w);
    split4(ec, h, l);
    *(uint2*)(p_ech + p) = h; *(uint2*)(p_ecl + p) = l;
    float4 eq = make_float4(e.x * qv.x, e.y * qv.y, e.z * qv.z, e.w * qv.w);
    split4(eq, h, l);
    *(uint2*)(p_eqh + p) = h; *(uint2*)(p_eql + p) = l;
}

// ---------------- reduce helpers ----------------
__device__ __forceinline__ float warpMax(float v) {
    #pragma unroll
    for (int o = 16; o > 0; o >>= 1) v = fmaxf(v, __shfl_xor_sync(0xffffffffu, v, o));
    return v;
}
__device__ __forceinline__ float warpSum(float v) {
    #pragma unroll
    for (int o = 16; o > 0; o >>= 1) v += __shfl_xor_sync(0xffffffffu, v, o);
    return v;
}

// ---------------- sc / sq ----------------
__global__ __launch_bounds__(256) void rowdot_kernel(
    const float* __restrict__ X, const float* __restrict__ w,
    const float* __restrict__ bias, int nrows, int which)
{
    int gw = (blockIdx.x * blockDim.x + threadIdx.x) >> 5;
    int lane = threadIdx.x & 31;
    if (gw >= nrows) return;
    const float* x = X + (size_t)gw * H_;
    float s = 0.f;
    #pragma unroll
    for (int i = 0; i < H_ / 32; i++)
        s = fmaf(x[lane + 32 * i], w[lane + 32 * i], s);
    s = warpSum(s);
    if (lane == 0) {
        float r = s + *bias;
        if (which == 0) g_sc[gw] = r; else g_sq[gw] = r;
    }
}

// ---------------- softmax: probs -> bf16 planes, record rowmax ----------------
__global__ __launch_bounds__(256) void softmax_kernel()
{
    const int row = blockIdx.x;
    const float* s = g_s + (size_t)row * Q_;
    const int tid = threadIdx.x;
    const int lane = tid & 31, w = tid >> 5;

    float v0 = s[tid], v1 = s[tid + 256];
    float m = warpMax(fmaxf(v0, v1));
    __shared__ float smx[8];
    if (lane == 0) smx[w] = m;
    __syncthreads();
    if (w == 0) {
        float t = smx[lane & 7];
        t = warpMax(t);
        if (lane == 0) smx[0] = t;
    }
    __syncthreads();
    m = smx[0];
    if (tid == 0) g_rowmax[row] = m;

    float e0 = __expf(v0 - m), e1 = __expf(v1 - m);
    float ss = warpSum(e0 + e1);
    __shared__ float ssm[8];
    if (lane == 0) ssm[w] = ss;
    __syncthreads();
    if (w == 0) {
        float t = (lane < 8) ? ssm[lane] : 0.f;
        t = warpSum(t);
        if (lane == 0) ssm[0] = t;
    }
    __syncthreads();
    float inv = 1.f / ssm[0];
    float p0 = e0 * inv, p1 = e1 * inv;
    size_t o = (size_t)row * Q_;
    __nv_bfloat16 h0 = __float2bfloat16(p0);
    __nv_bfloat16 h1 = __float2bfloat16(p1);
    p_ah[o + tid]       = h0;
    p_ah[o + tid + 256] = h1;
    p_al[o + tid]       = __float2bfloat16(p0 - __bfloat162float(h0));
    p_al[o + tid + 256] = __float2bfloat16(p1 - __bfloat162float(h1));
}

// ---------------- b_att ----------------
__global__ __launch_bounds__(1024) void batt_kernel()
{
    const int b = blockIdx.x;
    const float* rm = g_rowmax + b * C_;
    const int tid = threadIdx.x;
    const int lane = tid & 31, w = tid >> 5;

    float v0 = rm[tid], v1 = rm[tid + 1024];
    float m = warpMax(fmaxf(v0, v1));
    __shared__ float smx[32];
    if (lane == 0) smx[w] = m;
    __syncthreads();
    if (w == 0) {
        float t = smx[lane];
        t = warpMax(t);
        if (lane == 0) smx[0] = t;
    }
    __syncthreads();
    m = smx[0];

    float e0 = __expf(v0 - m), e1 = __expf(v1 - m);
    float ss = warpSum(e0 + e1);
    __shared__ float ssm[32];
    if (lane == 0) ssm[w] = ss;
    __syncthreads();
    if (w == 0) {
        float t = ssm[lane];
        t = warpSum(t);
        if (lane == 0) ssm[0] = t;
    }
    __syncthreads();
    float inv = 1.f / ssm[0];
    g_batt[b * C_ + tid]        = e0 * inv;
    g_batt[b * C_ + tid + 1024] = e1 * inv;
}

// ---------------- q2c ----------------
__global__ __launch_bounds__(256) void q2c_kernel(const float* __restrict__ emb2)
{
    const int b = blockIdx.y;
    const int h = blockIdx.x * 256 + threadIdx.x;
    __shared__ float batt[C_];
    for (int i = threadIdx.x; i < C_; i += 256) batt[i] = g_batt[b * C_ + i];
    __syncthreads();
    const float* e = emb2 + (size_t)b * C_ * H_ + h;
    float acc = 0.f;
    for (int c = 0; c < C_; c++)
        acc = fmaf(batt[c], e[(size_t)c * H_], acc);
    g_q2c[b * H_ + h] = acc;
}

// ---------------- warp-MMA GEMM (split-bf16, mma.sync m16n8k16) ----------------
// D[M x N] = A @ B^T (K-major rows both sides), hi/lo planes, 3 products.
// G=1: A=e2 planes (K=768),  B=b1 planes  -> g_s (+sc+sq+bcq)
// G=2: A=prob planes (K=512), B=e1t planes -> g_c2q
// G=3: A=4-seg planes (K=3072), B=w planes (rows<300) -> out (+b_red)
template<int G>
__global__ __launch_bounds__(256) void gemm_mma_kernel(const float* __restrict__ aux,
                                                       float* __restrict__ outp)
{
    extern __shared__ __align__(16) char smem[];
    const uint32_t sbase = smem_u32(smem);
    const int tid = threadIdx.x;
    const int lane = tid & 31, wid = tid >> 5;
    const int b  = blockIdx.z;
    const int m0 = blockIdx.x * BM;
    const int n0 = blockIdx.y * BN;
    const int m0w = (wid & 3) * 32;
    const int n0w = (wid >> 2) * 32;

    constexpr int KTOT = (G == 1) ? H_ : (G == 2) ? Q_ : K4_;
    constexpr int NC = KTOT / BK;

    // ---- loader lane mapping ----
    // A: 4 chunks of 16B per plane; B: 2 chunks per plane
    int aRow[4], aU[4]; uint32_t aSo[4];
    #pragma unroll
    for (int i = 0; i < 4; i++) {
        int t = tid + 256 * i;
        aRow[i] = t >> 3; aU[i] = t & 7;
        aSo[i] = SWZ((uint32_t)(aRow[i] * 128 + aU[i] * 16));
    }
    int bRow[2], bU[2]; uint32_t bSo[2];
    #pragma unroll
    for (int i = 0; i < 2; i++) {
        int t = tid + 256 * i;
        bRow[i] = t >> 3; bU[i] = t & 7;
        bSo[i] = SWZ((uint32_t)(bRow[i] * 128 + bU[i] * 16));
    }

    auto load_chunk = [&](int c, int st) {
        const uint32_t S = sbase + (uint32_t)st * STAGE_BYTES;
        const int k0 = c * BK;
        // ---- A ----
        const __nv_bfloat16 *pah, *pal;
        size_t abase; int strideA;
        if constexpr (G == 1) {
            pah = p_e2h; pal = p_e2l;
            abase = (size_t)(b * C_ + m0) * H_ + k0; strideA = H_;
        } else if constexpr (G == 2) {
            pah = p_ah; pal = p_al;
            abase = (size_t)(b * C_ + m0) * Q_ + k0; strideA = Q_;
        } else {
            int seg = k0 / H_;
            int koff = k0 - seg * H_;
            pah = (seg == 0) ? p_e2h : (seg == 1) ? p_cqh : (seg == 2) ? p_ech : p_eqh;
            pal = (seg == 0) ? p_e2l : (seg == 1) ? p_cql : (seg == 2) ? p_ecl : p_eql;
            abase = (size_t)(b * C_ + m0) * H_ + koff; strideA = H_;
        }
        #pragma unroll
        for (int i = 0; i < 4; i++) {
            size_t go = abase + (size_t)aRow[i] * strideA + aU[i] * 8;
            cpa16(S + aSo[i], pah + go);
            cpa16(S + OFF_AL + aSo[i], pal + go);
        }
        // ---- B ----
        if constexpr (G == 3) {
            #pragma unroll
            for (int i = 0; i < 2; i++) {
                int valid = (n0 + bRow[i]) < OUT_ ? 16 : 0;
                size_t go = (size_t)(n0 + bRow[i]) * K4_ + k0 + bU[i] * 8;
                cpa16z(S + OFF_BH + bSo[i], p_wh + go, valid);
                cpa16z(S + OFF_BL + bSo[i], p_wl + go, valid);
            }
        } else {
            const __nv_bfloat16 *pbh, *pbl;
            size_t bbase; int strideB;
            if constexpr (G == 1) {
                pbh = p_b1h; pbl = p_b1l;
                bbase = (size_t)(b * Q_ + n0) * H_ + k0; strideB = H_;
            } else {
                pbh = p_e1th; pbl = p_e1tl;
                bbase = (size_t)(b * H_ + n0) * Q_ + k0; strideB = Q_;
            }
            #pragma unroll
            for (int i = 0; i < 2; i++) {
                size_t go = bbase + (size_t)bRow[i] * strideB + bU[i] * 8;
                cpa16(S + OFF_BH + bSo[i], pbh + go);
                cpa16(S + OFF_BL + bSo[i], pbl + go);
            }
        }
    };

    // ---- mma lane constants ----
    const int matL = lane >> 3;
    const int rA   = lane & 7;
    const int rowA = (matL & 1) * 8 + rA;          // row within m16 tile
    const int kselA = (matL >> 1) * 16;            // byte sel within 32B kstep
    const int xA = rA << 4;
    const int nB   = (matL >> 1) * 8 + rA;         // row within n16 pair
    const int kselB = (matL & 1) * 16;
    const int xB = rA << 4;

    uint32_t aRowByte[2], bRowByte[2];
    #pragma unroll
    for (int mt = 0; mt < 2; mt++) aRowByte[mt] = (uint32_t)((m0w + mt * 16 + rowA) * 128);
    #pragma unroll
    for (int np = 0; np < 2; np++) bRowByte[np] = (uint32_t)((n0w + np * 16 + nB) * 128);

    float acc[2][4][4];
    #pragma unroll
    for (int mt = 0; mt < 2; mt++)
        #pragma unroll
        for (int nt = 0; nt < 4; nt++)
            #pragma unroll
            for (int k = 0; k < 4; k++) acc[mt][nt][k] = 0.f;

    auto compute_chunk = [&](uint32_t S) {
        #pragma unroll
        for (int p = 0; p < 3; p++) {
            const uint32_t Ab = S + (p == 2 ? OFF_AL : 0u);
            const uint32_t Bb = S + (p == 1 ? OFF_BL : OFF_BH);
            #pragma unroll
            for (int ks = 0; ks < 4; ks++) {
                uint32_t a[2][4], bf[2][4];
                const uint32_t kxA = (uint32_t)((ks * 32 + kselA) ^ xA);
                const uint32_t kxB = (uint32_t)((ks * 32 + kselB) ^ xB);
                #pragma unroll
                for (int mt = 0; mt < 2; mt++) ldsm4(a[mt], Ab + aRowByte[mt] + kxA);
                #pragma unroll
                for (int np = 0; np < 2; np++) ldsm4(bf[np], Bb + bRowByte[np] + kxB);
                #pragma unroll
                for (int mt = 0; mt < 2; mt++)
                    #pragma unroll
                    for (int nt = 0; nt < 4; nt++)
                        mma_bf16(acc[mt][nt], a[mt], bf[nt >> 1][(nt & 1) * 2], bf[nt >> 1][(nt & 1) * 2 + 1]);
            }
        }
    };

    // ---- pipeline ----
    load_chunk(0, 0);
    cpa_commit();
    for (int c = 0; c < NC; c++) {
        if (c + 1 < NC) {
            load_chunk(c + 1, (c + 1) & 1);
            cpa_commit();
            cpa_wait<1>();
        } else {
            cpa_wait<0>();
        }
        __syncthreads();
        compute_chunk(sbase + (uint32_t)(c & 1) * STAGE_BYTES);
        __syncthreads();
    }

    // ---- epilogue ----
    const int r0l = lane >> 2;
    const int c0l = (lane & 3) * 2;
    #pragma unroll
    for (int mt = 0; mt < 2; mt++) {
        #pragma unroll
        for (int nt = 0; nt < 4; nt++) {
            int rg = b * C_ + m0 + m0w + mt * 16 + r0l;
            int cg = n0 + n0w + nt * 8 + c0l;
            float d0 = acc[mt][nt][0], d1 = acc[mt][nt][1];
            float d2 = acc[mt][nt][2], d3 = acc[mt][nt][3];
            if constexpr (G == 1) {
                float bcq = aux[0];
                float sq0 = g_sq[b * Q_ + cg], sq1 = g_sq[b * Q_ + cg + 1];
                float sc0 = g_sc[rg], sc1 = g_sc[rg + 8];
                *(float2*)(g_s + (size_t)rg * Q_ + cg)       = make_float2(d0 + sc0 + sq0 + bcq, d1 + sc0 + sq1 + bcq);
                *(float2*)(g_s + (size_t)(rg + 8) * Q_ + cg) = make_float2(d2 + sc1 + sq0 + bcq, d3 + sc1 + sq1 + bcq);
            } else if constexpr (G == 2) {
                *(float2*)(g_c2q + (size_t)rg * H_ + cg)       = make_float2(d0, d1);
                *(float2*)(g_c2q + (size_t)(rg + 8) * H_ + cg) = make_float2(d2, d3);
            } else {
                if (cg < OUT_) {
                    float b0 = aux[cg], b1 = aux[cg + 1];
                    *(float2*)(outp + (size_t)rg * OUT_ + cg)       = make_float2(d0 + b0, d1 + b1);
                    *(float2*)(outp + (size_t)(rg + 8) * OUT_ + cg) = make_float2(d2 + b0, d3 + b1);
                }
            }
        }
    }
}

// ---------------- launch ----------------
extern "C" void kernel_launch(void* const* d_in, const int* in_sizes, int n_in,
                              void* d_out, int out_size)
{
    const float* emb1  = (const float*)d_in[0];
    const float* emb2  = (const float*)d_in[1];
    const float* w_c   = (const float*)d_in[2];
    const float* b_c   = (const float*)d_in[3];
    const float* w_q   = (const float*)d_in[4];
    const float* b_q   = (const float*)d_in[5];
    const float* w_cq  = (const float*)d_in[6];
    const float* b_cq  = (const float*)d_in[7];
    const float* w_red = (const float*)d_in[8];
    const float* b_red = (const float*)d_in[9];
    float* out = (float*)d_out;

    cudaFuncSetAttribute(gemm_mma_kernel<1>, cudaFuncAttributeMaxDynamicSharedMemorySize, SMEM_TOTAL);
    cudaFuncSetAttribute(gemm_mma_kernel<2>, cudaFuncAttributeMaxDynamicSharedMemorySize, SMEM_TOTAL);
    cudaFuncSetAttribute(gemm_mma_kernel<3>, cudaFuncAttributeMaxDynamicSharedMemorySize, SMEM_TOTAL);

    // planes prep + small dots
    prep_emb2_kernel<<<(int)((size_t)B_ * C_ * H_ / 4 / 256), 256>>>(emb2);
    prep_b1_kernel<<<(int)((size_t)B_ * Q_ * H_ / 4 / 256), 256>>>(emb1, w_cq);
    prep_e1t_kernel<<<dim3(Q_ / 32, H_ / 32, B_), 256>>>(emb1);
    prep_wred_kernel<<<(int)((size_t)OUT_ * K4_ / 4 / 256), 256>>>(w_red);
    rowdot_kernel<<<(B_ * C_ * 32) / 256, 256>>>(emb2, w_c, b_c, B_ * C_, 0);
    rowdot_kernel<<<(B_ * Q_ * 32) / 256, 256>>>(emb1, w_q, b_q, B_ * Q_, 1);

    // GEMM1: s = emb2 @ (emb1*w_cq)^T + sc + sq + bcq
    gemm_mma_kernel<1><<<dim3(C_ / BM, Q_ / BN, B_), 256, SMEM_TOTAL>>>(b_cq, nullptr);

    // softmax (probs -> planes), batt, q2c
    softmax_kernel<<<B_ * C_, 256>>>();
    batt_kernel<<<B_, 1024>>>();
    q2c_kernel<<<dim3(H_ / 256, B_), 256>>>(emb2);

    // GEMM2: c2q = a @ emb1
    gemm_mma_kernel<2><<<dim3(C_ / BM, H_ / BN, B_), 256, SMEM_TOTAL>>>(nullptr, nullptr);

    // GEMM3 prep + GEMM3
    prep_g3_kernel<<<(int)((size_t)B_ * C_ * H_ / 4 / 256), 256>>>(emb2);
    gemm_mma_kernel<3><<<dim3(C_ / BM, (OUT_ + BN - 1) / BN, B_), 256, SMEM_TOTAL>>>(b_red, out);
}

// round 5
// speedup vs baseline: 3.9366x; 1.4325x over previous
#include <cuda_runtime.h>
#include <cuda_bf16.h>
#include <cstdint>

// ---------------- problem constants ----------------
#define B_   8
#define Q_   512
#define C_   2048
#define H_   768
#define OUT_ 300
#define K4_  3072   // 4*H
#define K3_  2304   // 3*H (GEMM3 after seg-4 fold)

// ---------------- GEMM tiling ----------------
#define BM 128
#define BN 64
#define BK 64                  // bf16 k per chunk (128B rows)
#define OFF_AL 16384
#define OFF_BH 32768
#define OFF_BL 40960
#define STAGE_BYTES 49152
#define SMEM_TOTAL (2 * STAGE_BYTES)   // 96 KB

#define SWZ(x) ((x) ^ (((x) >> 3) & 0x70))

// ---------------- f32 scratch ----------------
static __device__ __align__(16) float g_s[(size_t)B_ * C_ * Q_];
static __device__ float g_sc[B_ * C_];
static __device__ float g_sq[B_ * Q_];
static __device__ float g_rowmax[B_ * C_];
static __device__ float g_batt[B_ * C_];
static __device__ float g_q2c[B_ * H_];

// ---------------- bf16 hi/lo planes ----------------
static __device__ __align__(16) __nv_bfloat16 p_e2h[(size_t)B_ * C_ * H_];
static __device__ __align__(16) __nv_bfloat16 p_e2l[(size_t)B_ * C_ * H_];
static __device__ __align__(16) __nv_bfloat16 p_b1h[(size_t)B_ * Q_ * H_];   // emb1*w_cq
static __device__ __align__(16) __nv_bfloat16 p_b1l[(size_t)B_ * Q_ * H_];
static __device__ __align__(16) __nv_bfloat16 p_e1th[(size_t)B_ * H_ * Q_];  // emb1^T
static __device__ __align__(16) __nv_bfloat16 p_e1tl[(size_t)B_ * H_ * Q_];
static __device__ __align__(16) __nv_bfloat16 p_ah[(size_t)B_ * C_ * Q_];    // softmax probs
static __device__ __align__(16) __nv_bfloat16 p_al[(size_t)B_ * C_ * Q_];
static __device__ __align__(16) __nv_bfloat16 p_cqh[(size_t)B_ * C_ * H_];   // c2q
static __device__ __align__(16) __nv_bfloat16 p_cql[(size_t)B_ * C_ * H_];
static __device__ __align__(16) __nv_bfloat16 p_ech[(size_t)B_ * C_ * H_];   // emb2*c2q
static __device__ __align__(16) __nv_bfloat16 p_ecl[(size_t)B_ * C_ * H_];
static __device__ __align__(16) __nv_bfloat16 p_w14h[(size_t)B_ * OUT_ * H_]; // w1 + w4*q2c[b]
static __device__ __align__(16) __nv_bfloat16 p_w14l[(size_t)B_ * OUT_ * H_];
static __device__ __align__(16) __nv_bfloat16 p_w23h[(size_t)OUT_ * 2 * H_];  // w2|w3
static __device__ __align__(16) __nv_bfloat16 p_w23l[(size_t)OUT_ * 2 * H_];

// ---------------- asm helpers ----------------
__device__ __forceinline__ uint32_t smem_u32(const void* p) {
    uint32_t a;
    asm("{ .reg .u64 t; cvta.to.shared.u64 t, %1; cvt.u32.u64 %0, t; }" : "=r"(a) : "l"(p));
    return a;
}
__device__ __forceinline__ void cpa16(uint32_t dst, const void* src) {
    asm volatile("cp.async.cg.shared.global [%0], [%1], 16;" :: "r"(dst), "l"(src) : "memory");
}
__device__ __forceinline__ void cpa16z(uint32_t dst, const void* src, int szbytes) {
    asm volatile("cp.async.cg.shared.global [%0], [%1], 16, %2;" :: "r"(dst), "l"(src), "r"(szbytes) : "memory");
}
__device__ __forceinline__ void cpa_commit() {
    asm volatile("cp.async.commit_group;" ::: "memory");
}
template<int N>
__device__ __forceinline__ void cpa_wait() {
    asm volatile("cp.async.wait_group %0;" :: "n"(N) : "memory");
}
__device__ __forceinline__ void ldsm4(uint32_t (&r)[4], uint32_t addr) {
    asm volatile("ldmatrix.sync.aligned.m8n8.x4.shared.b16 {%0,%1,%2,%3}, [%4];"
        : "=r"(r[0]), "=r"(r[1]), "=r"(r[2]), "=r"(r[3]) : "r"(addr));
}
__device__ __forceinline__ void mma_bf16(float (&d)[4], const uint32_t (&a)[4], uint32_t b0, uint32_t b1) {
    asm volatile("mma.sync.aligned.m16n8k16.row.col.f32.bf16.bf16.f32 "
        "{%0,%1,%2,%3}, {%4,%5,%6,%7}, {%8,%9}, {%0,%1,%2,%3};"
        : "+f"(d[0]), "+f"(d[1]), "+f"(d[2]), "+f"(d[3])
        : "r"(a[0]), "r"(a[1]), "r"(a[2]), "r"(a[3]), "r"(b0), "r"(b1));
}

// ---------------- split helpers ----------------
__device__ __forceinline__ void split4(float4 v, uint2& hi, uint2& lo) {
    __nv_bfloat162 h01 = __floats2bfloat162_rn(v.x, v.y);
    __nv_bfloat162 h23 = __floats2bfloat162_rn(v.z, v.w);
    float lx = v.x - __bfloat162float(h01.x);
    float ly = v.y - __bfloat162float(h01.y);
    float lz = v.z - __bfloat162float(h23.x);
    float lw = v.w - __bfloat162float(h23.y);
    __nv_bfloat162 l01 = __floats2bfloat162_rn(lx, ly);
    __nv_bfloat162 l23 = __floats2bfloat162_rn(lz, lw);
    hi.x = *(uint32_t*)&h01; hi.y = *(uint32_t*)&h23;
    lo.x = *(uint32_t*)&l01; lo.y = *(uint32_t*)&l23;
}
__device__ __forceinline__ void write_pair(__nv_bfloat16* ph, __nv_bfloat16* pl,
                                           size_t o, float x, float y) {
    __nv_bfloat162 h = __floats2bfloat162_rn(x, y);
    __nv_bfloat162 l = __floats2bfloat162_rn(x - __bfloat162float(h.x),
                                             y - __bfloat162float(h.y));
    *(__nv_bfloat162*)(ph + o) = h;
    *(__nv_bfloat162*)(pl + o) = l;
}

// ---------------- prep kernels ----------------
__global__ __launch_bounds__(256) void prep_emb2_kernel(const float* __restrict__ emb2) {
    size_t p = ((size_t)blockIdx.x * 256 + threadIdx.x) * 4;
    float4 v = *(const float4*)(emb2 + p);
    uint2 h, l; split4(v, h, l);
    *(uint2*)(p_e2h + p) = h;
    *(uint2*)(p_e2l + p) = l;
}

__global__ __launch_bounds__(256) void prep_b1_kernel(const float* __restrict__ emb1,
                                                      const float* __restrict__ w_cq) {
    size_t p = ((size_t)blockIdx.x * 256 + threadIdx.x) * 4;
    int hcol = (int)(p % H_);
    float4 v = *(const float4*)(emb1 + p);
    float4 w = *(const float4*)(w_cq + hcol);
    v.x *= w.x; v.y *= w.y; v.z *= w.z; v.w *= w.w;
    uint2 h, l; split4(v, h, l);
    *(uint2*)(p_b1h + p) = h;
    *(uint2*)(p_b1l + p) = l;
}

// emb1^T split: e1t[b,h,q] = emb1[b,q,h]
__global__ __launch_bounds__(256) void prep_e1t_kernel(const float* __restrict__ emb1) {
    __shared__ float sm[32][33];
    const int b = blockIdx.z, h0 = blockIdx.y * 32, q0 = blockIdx.x * 32;
    const int tx = threadIdx.x & 31, ty = threadIdx.x >> 5;
    #pragma unroll
    for (int i = 0; i < 4; i++)
        sm[ty + 8 * i][tx] = emb1[(size_t)(b * Q_ + q0 + ty + 8 * i) * H_ + h0 + tx];
    __syncthreads();
    #pragma unroll
    for (int i = 0; i < 4; i++) {
        float v = sm[tx][ty + 8 * i];
        __nv_bfloat16 h = __float2bfloat16(v);
        __nv_bfloat16 l = __float2bfloat16(v - __bfloat162float(h));
        size_t o = (size_t)(b * H_ + h0 + ty + 8 * i) * Q_ + q0 + tx;
        p_e1th[o] = h;
        p_e1tl[o] = l;
    }
}

// w2|w3 planes: p_w23[n, 0:1536] = w_red[n, 768:2304]
__global__ __launch_bounds__(256) void prep_w23_kernel(const float* __restrict__ w_red) {
    size_t p = ((size_t)blockIdx.x * 256 + threadIdx.x) * 4;    // over OUT_*1536
    int col = (int)(p % (2 * H_));
    int n = (int)(p / (2 * H_));
    float4 v = *(const float4*)(w_red + (size_t)n * K4_ + H_ + col);
    uint2 h, l; split4(v, h, l);
    *(uint2*)(p_w23h + p) = h;
    *(uint2*)(p_w23l + p) = l;
}

// w14[b,n,h] = w1[n,h] + w4[n,h] * q2c[b,h]   (folds segment-4 GEMM into segment-1)
__global__ __launch_bounds__(256) void prep_w14_kernel(const float* __restrict__ w_red) {
    size_t p = ((size_t)blockIdx.x * 256 + threadIdx.x) * 4;    // over B_*OUT_*H_
    int h = (int)(p % H_);
    int n = (int)((p / H_) % OUT_);
    int b = (int)(p / ((size_t)OUT_ * H_));
    float4 w1 = *(const float4*)(w_red + (size_t)n * K4_ + h);
    float4 w4 = *(const float4*)(w_red + (size_t)n * K4_ + 3 * H_ + h);
    float4 q  = *(const float4*)(g_q2c + b * H_ + h);
    float4 v = make_float4(w1.x + w4.x * q.x, w1.y + w4.y * q.y,
                           w1.z + w4.z * q.z, w1.w + w4.w * q.w);
    uint2 hh, ll; split4(v, hh, ll);
    *(uint2*)(p_w14h + p) = hh;
    *(uint2*)(p_w14l + p) = ll;
}

// ---------------- reduce helpers ----------------
__device__ __forceinline__ float warpMax(float v) {
    #pragma unroll
    for (int o = 16; o > 0; o >>= 1) v = fmaxf(v, __shfl_xor_sync(0xffffffffu, v, o));
    return v;
}
__device__ __forceinline__ float warpSum(float v) {
    #pragma unroll
    for (int o = 16; o > 0; o >>= 1) v += __shfl_xor_sync(0xffffffffu, v, o);
    return v;
}

// ---------------- sc / sq ----------------
__global__ __launch_bounds__(256) void rowdot_kernel(
    const float* __restrict__ X, const float* __restrict__ w,
    const float* __restrict__ bias, int nrows, int which)
{
    int gw = (blockIdx.x * blockDim.x + threadIdx.x) >> 5;
    int lane = threadIdx.x & 31;
    if (gw >= nrows) return;
    const float* x = X + (size_t)gw * H_;
    float s = 0.f;
    #pragma unroll
    for (int i = 0; i < H_ / 32; i++)
        s = fmaf(x[lane + 32 * i], w[lane + 32 * i], s);
    s = warpSum(s);
    if (lane == 0) {
        float r = s + *bias;
        if (which == 0) g_sc[gw] = r; else g_sq[gw] = r;
    }
}

// ---------------- softmax: probs -> bf16 planes, record rowmax ----------------
__global__ __launch_bounds__(256) void softmax_kernel()
{
    const int row = blockIdx.x;
    const float* s = g_s + (size_t)row * Q_;
    const int tid = threadIdx.x;
    const int lane = tid & 31, w = tid >> 5;

    float v0 = s[tid], v1 = s[tid + 256];
    float m = warpMax(fmaxf(v0, v1));
    __shared__ float smx[8];
    if (lane == 0) smx[w] = m;
    __syncthreads();
    if (w == 0) {
        float t = smx[lane & 7];
        t = warpMax(t);
        if (lane == 0) smx[0] = t;
    }
    __syncthreads();
    m = smx[0];
    if (tid == 0) g_rowmax[row] = m;

    float e0 = __expf(v0 - m), e1 = __expf(v1 - m);
    float ss = warpSum(e0 + e1);
    __shared__ float ssm[8];
    if (lane == 0) ssm[w] = ss;
    __syncthreads();
    if (w == 0) {
        float t = (lane < 8) ? ssm[lane] : 0.f;
        t = warpSum(t);
        if (lane == 0) ssm[0] = t;
    }
    __syncthreads();
    float inv = 1.f / ssm[0];
    float p0 = e0 * inv, p1 = e1 * inv;
    size_t o = (size_t)row * Q_;
    __nv_bfloat16 h0 = __float2bfloat16(p0);
    __nv_bfloat16 h1 = __float2bfloat16(p1);
    p_ah[o + tid]       = h0;
    p_ah[o + tid + 256] = h1;
    p_al[o + tid]       = __float2bfloat16(p0 - __bfloat162float(h0));
    p_al[o + tid + 256] = __float2bfloat16(p1 - __bfloat162float(h1));
}

// ---------------- b_att ----------------
__global__ __launch_bounds__(1024) void batt_kernel()
{
    const int b = blockIdx.x;
    const float* rm = g_rowmax + b * C_;
    const int tid = threadIdx.x;
    const int lane = tid & 31, w = tid >> 5;

    float v0 = rm[tid], v1 = rm[tid + 1024];
    float m = warpMax(fmaxf(v0, v1));
    __shared__ float smx[32];
    if (lane == 0) smx[w] = m;
    __syncthreads();
    if (w == 0) {
        float t = smx[lane];
        t = warpMax(t);
        if (lane == 0) smx[0] = t;
    }
    __syncthreads();
    m = smx[0];

    float e0 = __expf(v0 - m), e1 = __expf(v1 - m);
    float ss = warpSum(e0 + e1);
    __shared__ float ssm[32];
    if (lane == 0) ssm[w] = ss;
    __syncthreads();
    if (w == 0) {
        float t = ssm[lane];
        t = warpSum(t);
        if (lane == 0) ssm[0] = t;
    }
    __syncthreads();
    float inv = 1.f / ssm[0];
    g_batt[b * C_ + tid]        = e0 * inv;
    g_batt[b * C_ + tid + 1024] = e1 * inv;
}

// ---------------- q2c (split C, atomic accumulate) ----------------
__global__ __launch_bounds__(256) void q2c_zero_kernel() {
    g_q2c[blockIdx.x * 256 + threadIdx.x] = 0.f;
}
__global__ __launch_bounds__(256) void q2c_kernel(const float* __restrict__ emb2)
{
    const int b = blockIdx.y;
    const int h = blockIdx.x * 256 + threadIdx.x;
    const int c0 = blockIdx.z * 256;
    __shared__ float batt[256];
    batt[threadIdx.x] = g_batt[b * C_ + c0 + threadIdx.x];
    __syncthreads();
    const float* e = emb2 + (size_t)(b * C_ + c0) * H_ + h;
    float acc = 0.f;
    #pragma unroll 8
    for (int c = 0; c < 256; c++)
        acc = fmaf(batt[c], e[(size_t)c * H_], acc);
    atomicAdd(&g_q2c[b * H_ + h], acc);
}

// ---------------- warp-MMA GEMM (split-bf16, mma.sync m16n8k16) ----------------
// D[M x N] = A @ B^T (K-major rows both sides), hi/lo planes, 3 products.
// G=1: A=e2 planes (K=768),   B=b1 planes              -> g_s (+sc+sq+bcq)
// G=2: A=prob planes (K=512), B=e1t planes             -> cq/ec planes (fused split epilogue)
// G=3: A=[e2|cq|ec] (K=2304), B=[w14(b)|w23] (rows<300) -> out (+b_red)
template<int G>
__global__ __launch_bounds__(256) void gemm_mma_kernel(const float* __restrict__ aux,
                                                       float* __restrict__ outp)
{
    extern __shared__ __align__(16) char smem[];
    const uint32_t sbase = smem_u32(smem);
    const int tid = threadIdx.x;
    const int lane = tid & 31, wid = tid >> 5;
    const int b  = blockIdx.z;
    const int m0 = blockIdx.x * BM;
    const int n0 = blockIdx.y * BN;
    const int m0w = (wid & 3) * 32;
    const int n0w = (wid >> 2) * 32;

    constexpr int KTOT = (G == 1) ? H_ : (G == 2) ? Q_ : K3_;
    constexpr int NC = KTOT / BK;

    // ---- loader lane mapping ----
    int aRow[4], aU[4]; uint32_t aSo[4];
    #pragma unroll
    for (int i = 0; i < 4; i++) {
        int t = tid + 256 * i;
        aRow[i] = t >> 3; aU[i] = t & 7;
        aSo[i] = SWZ((uint32_t)(aRow[i] * 128 + aU[i] * 16));
    }
    int bRow[2], bU[2]; uint32_t bSo[2];
    #pragma unroll
    for (int i = 0; i < 2; i++) {
        int t = tid + 256 * i;
        bRow[i] = t >> 3; bU[i] = t & 7;
        bSo[i] = SWZ((uint32_t)(bRow[i] * 128 + bU[i] * 16));
    }

    auto load_chunk = [&](int c, int st) {
        const uint32_t S = sbase + (uint32_t)st * STAGE_BYTES;
        const int k0 = c * BK;
        // ---- A ----
        const __nv_bfloat16 *pah, *pal;
        size_t abase; int strideA;
        if constexpr (G == 1) {
            pah = p_e2h; pal = p_e2l;
            abase = (size_t)(b * C_ + m0) * H_ + k0; strideA = H_;
        } else if constexpr (G == 2) {
            pah = p_ah; pal = p_al;
            abase = (size_t)(b * C_ + m0) * Q_ + k0; strideA = Q_;
        } else {
            int seg = k0 / H_;
            int koff = k0 - seg * H_;
            pah = (seg == 0) ? p_e2h : (seg == 1) ? p_cqh : p_ech;
            pal = (seg == 0) ? p_e2l : (seg == 1) ? p_cql : p_ecl;
            abase = (size_t)(b * C_ + m0) * H_ + koff; strideA = H_;
        }
        #pragma unroll
        for (int i = 0; i < 4; i++) {
            size_t go = abase + (size_t)aRow[i] * strideA + aU[i] * 8;
            cpa16(S + aSo[i], pah + go);
            cpa16(S + OFF_AL + aSo[i], pal + go);
        }
        // ---- B ----
        if constexpr (G == 3) {
            int seg = k0 / H_;
            #pragma unroll
            for (int i = 0; i < 2; i++) {
                int nrow = n0 + bRow[i];
                int valid = nrow < OUT_ ? 16 : 0;
                int nr = nrow < OUT_ ? nrow : (OUT_ - 1);
                const __nv_bfloat16 *pbh, *pbl;
                size_t go;
                if (seg == 0) {
                    pbh = p_w14h; pbl = p_w14l;
                    go = ((size_t)b * OUT_ + nr) * H_ + k0 + bU[i] * 8;
                } else {
                    pbh = p_w23h; pbl = p_w23l;
                    go = (size_t)nr * (2 * H_) + (k0 - H_) + bU[i] * 8;
                }
                cpa16z(S + OFF_BH + bSo[i], pbh + go, valid);
                cpa16z(S + OFF_BL + bSo[i], pbl + go, valid);
            }
        } else {
            const __nv_bfloat16 *pbh, *pbl;
            size_t bbase; int strideB;
            if constexpr (G == 1) {
                pbh = p_b1h; pbl = p_b1l;
                bbase = (size_t)(b * Q_ + n0) * H_ + k0; strideB = H_;
            } else {
                pbh = p_e1th; pbl = p_e1tl;
                bbase = (size_t)(b * H_ + n0) * Q_ + k0; strideB = Q_;
            }
            #pragma unroll
            for (int i = 0; i < 2; i++) {
                size_t go = bbase + (size_t)bRow[i] * strideB + bU[i] * 8;
                cpa16(S + OFF_BH + bSo[i], pbh + go);
                cpa16(S + OFF_BL + bSo[i], pbl + go);
            }
        }
    };

    // ---- mma lane constants ----
    const int matL = lane >> 3;
    const int rA   = lane & 7;
    const int rowA = (matL & 1) * 8 + rA;
    const int kselA = (matL >> 1) * 16;
    const int xA = rA << 4;
    const int nB   = (matL >> 1) * 8 + rA;
    const int kselB = (matL & 1) * 16;
    const int xB = rA << 4;

    uint32_t aRowByte[2], bRowByte[2];
    #pragma unroll
    for (int mt = 0; mt < 2; mt++) aRowByte[mt] = (uint32_t)((m0w + mt * 16 + rowA) * 128);
    #pragma unroll
    for (int np = 0; np < 2; np++) bRowByte[np] = (uint32_t)((n0w + np * 16 + nB) * 128);

    float acc[2][4][4];
    #pragma unroll
    for (int mt = 0; mt < 2; mt++)
        #pragma unroll
        for (int nt = 0; nt < 4; nt++)
            #pragma unroll
            for (int k = 0; k < 4; k++) acc[mt][nt][k] = 0.f;

    auto compute_chunk = [&](uint32_t S) {
        #pragma unroll
        for (int ks = 0; ks < 4; ks++) {
            uint32_t aH[2][4], aL[2][4], bH[2][4], bL[2][4];
            const uint32_t kxA = (uint32_t)((ks * 32 + kselA) ^ xA);
            const uint32_t kxB = (uint32_t)((ks * 32 + kselB) ^ xB);
            #pragma unroll
            for (int mt = 0; mt < 2; mt++) {
                ldsm4(aH[mt], S + aRowByte[mt] + kxA);
                ldsm4(aL[mt], S + OFF_AL + aRowByte[mt] + kxA);
            }
            #pragma unroll
            for (int np = 0; np < 2; np++) {
                ldsm4(bH[np], S + OFF_BH + bRowByte[np] + kxB);
                ldsm4(bL[np], S + OFF_BL + bRowByte[np] + kxB);
            }
            #pragma unroll
            for (int mt = 0; mt < 2; mt++)
                #pragma unroll
                for (int nt = 0; nt < 4; nt++) {
                    uint32_t b0h = bH[nt >> 1][(nt & 1) * 2], b1h = bH[nt >> 1][(nt & 1) * 2 + 1];
                    uint32_t b0l = bL[nt >> 1][(nt & 1) * 2], b1l = bL[nt >> 1][(nt & 1) * 2 + 1];
                    mma_bf16(acc[mt][nt], aH[mt], b0h, b1h);
                    mma_bf16(acc[mt][nt], aH[mt], b0l, b1l);
                    mma_bf16(acc[mt][nt], aL[mt], b0h, b1h);
                }
        }
    };

    // ---- pipeline ----
    load_chunk(0, 0);
    cpa_commit();
    for (int c = 0; c < NC; c++) {
        if (c + 1 < NC) {
            load_chunk(c + 1, (c + 1) & 1);
            cpa_commit();
            cpa_wait<1>();
        } else {
            cpa_wait<0>();
        }
        __syncthreads();
        compute_chunk(sbase + (uint32_t)(c & 1) * STAGE_BYTES);
        __syncthreads();
    }

    // ---- epilogue ----
    const int r0l = lane >> 2;
    const int c0l = (lane & 3) * 2;
    #pragma unroll
    for (int mt = 0; mt < 2; mt++) {
        #pragma unroll
        for (int nt = 0; nt < 4; nt++) {
            int rg = b * C_ + m0 + m0w + mt * 16 + r0l;
            int cg = n0 + n0w + nt * 8 + c0l;
            float d0 = acc[mt][nt][0], d1 = acc[mt][nt][1];
            float d2 = acc[mt][nt][2], d3 = acc[mt][nt][3];
            if constexpr (G == 1) {
                float bcq = aux[0];
                float sq0 = g_sq[b * Q_ + cg], sq1 = g_sq[b * Q_ + cg + 1];
                float sc0 = g_sc[rg], sc1 = g_sc[rg + 8];
                *(float2*)(g_s + (size_t)rg * Q_ + cg)       = make_float2(d0 + sc0 + sq0 + bcq, d1 + sc0 + sq1 + bcq);
                *(float2*)(g_s + (size_t)(rg + 8) * Q_ + cg) = make_float2(d2 + sc1 + sq0 + bcq, d3 + sc1 + sq1 + bcq);
            } else if constexpr (G == 2) {
                size_t o0 = (size_t)rg * H_ + cg;
                size_t o1 = (size_t)(rg + 8) * H_ + cg;
                float2 e0 = *(const float2*)(aux + o0);     // emb2
                float2 e1 = *(const float2*)(aux + o1);
                write_pair(p_cqh, p_cql, o0, d0, d1);
                write_pair(p_cqh, p_cql, o1, d2, d3);
                write_pair(p_ech, p_ecl, o0, d0 * e0.x, d1 * e0.y);
                write_pair(p_ech, p_ecl, o1, d2 * e1.x, d3 * e1.y);
            } else {
                if (cg < OUT_) {
                    float b0 = aux[cg], b1 = aux[cg + 1];
                    *(float2*)(outp + (size_t)rg * OUT_ + cg)       = make_float2(d0 + b0, d1 + b1);
                    *(float2*)(outp + (size_t)(rg + 8) * OUT_ + cg) = make_float2(d2 + b0, d3 + b1);
                }
            }
        }
    }
}

// ---------------- launch ----------------
extern "C" void kernel_launch(void* const* d_in, const int* in_sizes, int n_in,
                              void* d_out, int out_size)
{
    const float* emb1  = (const float*)d_in[0];
    const float* emb2  = (const float*)d_in[1];
    const float* w_c   = (const float*)d_in[2];
    const float* b_c   = (const float*)d_in[3];
    const float* w_q   = (const float*)d_in[4];
    const float* b_q   = (const float*)d_in[5];
    const float* w_cq  = (const float*)d_in[6];
    const float* b_cq  = (const float*)d_in[7];
    const float* w_red = (const float*)d_in[8];
    const float* b_red = (const float*)d_in[9];
    float* out = (float*)d_out;

    cudaFuncSetAttribute(gemm_mma_kernel<1>, cudaFuncAttributeMaxDynamicSharedMemorySize, SMEM_TOTAL);
    cudaFuncSetAttribute(gemm_mma_kernel<2>, cudaFuncAttributeMaxDynamicSharedMemorySize, SMEM_TOTAL);
    cudaFuncSetAttribute(gemm_mma_kernel<3>, cudaFuncAttributeMaxDynamicSharedMemorySize, SMEM_TOTAL);

    // planes prep + small dots
    prep_emb2_kernel<<<(int)((size_t)B_ * C_ * H_ / 4 / 256), 256>>>(emb2);
    prep_b1_kernel<<<(int)((size_t)B_ * Q_ * H_ / 4 / 256), 256>>>(emb1, w_cq);
    prep_e1t_kernel<<<dim3(Q_ / 32, H_ / 32, B_), 256>>>(emb1);
    prep_w23_kernel<<<(int)((size_t)OUT_ * 2 * H_ / 4 / 256), 256>>>(w_red);
    rowdot_kernel<<<(B_ * C_ * 32) / 256, 256>>>(emb2, w_c, b_c, B_ * C_, 0);
    rowdot_kernel<<<(B_ * Q_ * 32) / 256, 256>>>(emb1, w_q, b_q, B_ * Q_, 1);

    // GEMM1: s = emb2 @ (emb1*w_cq)^T + sc + sq + bcq
    gemm_mma_kernel<1><<<dim3(C_ / BM, Q_ / BN, B_), 256, SMEM_TOTAL>>>(b_cq, nullptr);

    // softmax (probs -> planes), batt, q2c, per-batch fused weights
    softmax_kernel<<<B_ * C_, 256>>>();
    batt_kernel<<<B_, 1024>>>();
    q2c_zero_kernel<<<B_ * H_ / 256, 256>>>();
    q2c_kernel<<<dim3(H_ / 256, B_, C_ / 256), 256>>>(emb2);
    prep_w14_kernel<<<(int)((size_t)B_ * OUT_ * H_ / 4 / 256), 256>>>(w_red);

    // GEMM2: c2q = a @ emb1  (epilogue writes cq / e2*cq planes directly)
    gemm_mma_kernel<2><<<dim3(C_ / BM, H_ / BN, B_), 256, SMEM_TOTAL>>>(emb2, nullptr);

    // GEMM3: out = [e2 | cq | e2*cq] @ [w14(b) | w2 | w3]^T + b_red
    gemm_mma_kernel<3><<<dim3(C_ / BM, (OUT_ + BN - 1) / BN, B_), 256, SMEM_TOTAL>>>(b_red, out);
}